// round 1
// baseline (speedup 1.0000x reference)
#include <cuda_runtime.h>
#include <mma.h>
#include <math.h>

using namespace nvcuda;

#define N_TOK 2048
#define HID   2880
#define QKV_N 5120   // 64*64 q + 8*64 k + 8*64 v
#define ADIM  4096   // 64 heads * 64 dim
#define SM_SCALE 0.125f

// ---------------- scratch (no allocs allowed) ----------------
__device__ float g_t[N_TOK * HID];      // rmsnorm output
__device__ float g_qkv[N_TOK * QKV_N];  // qkv projection (rope applied in place)
__device__ float g_attn[N_TOK * ADIM];  // attention output

// ---------------- RMSNorm ----------------
__global__ __launch_bounds__(256) void rmsnorm_kernel(
    const float* __restrict__ x, const float* __restrict__ w, float* __restrict__ t) {
  int row = blockIdx.x;
  const float* xr = x + (size_t)row * HID;
  float* tr = t + (size_t)row * HID;
  float ss = 0.f;
  for (int i = threadIdx.x; i < HID; i += 256) { float v = xr[i]; ss += v * v; }
  #pragma unroll
  for (int o = 16; o; o >>= 1) ss += __shfl_xor_sync(0xffffffffu, ss, o);
  __shared__ float red[8];
  __shared__ float s_inv;
  if ((threadIdx.x & 31) == 0) red[threadIdx.x >> 5] = ss;
  __syncthreads();
  if (threadIdx.x == 0) {
    float tot = 0.f;
    #pragma unroll
    for (int i = 0; i < 8; i++) tot += red[i];
    s_inv = rsqrtf(tot / (float)HID + 1e-5f);
  }
  __syncthreads();
  float inv = s_inv;
  for (int i = threadIdx.x; i < HID; i += 256) tr[i] = xr[i] * inv * w[i];
}

// ---------------- RoPE (YaRN/NTK), in place on q (heads 0..63) and k (heads 64..71) ----------------
__global__ void rope_kernel(float* __restrict__ qkv) {
  int idx = blockIdx.x * blockDim.x + threadIdx.x;
  if (idx >= N_TOK * 72 * 32) return;
  int p = idx & 31;                // dim pair 0..31
  int h = (idx >> 5) % 72;         // head slot (q:0..63, k:64..71; both at offset h*64)
  int n = idx / (32 * 72);         // token

  const double LOGB = 11.918390573078392;  // ln(150000)
  double freq = exp((double)p * (LOGB / 32.0));
  double interp = 1.0 / (32.0 * freq);
  double extrap = 1.0 / freq;
  double low  = 32.0 * log(4096.0 / (32.0 * 2.0 * M_PI)) / LOGB;
  double high = 32.0 * log(4096.0 / (2.0 * M_PI)) / LOGB;
  double ramp = ((double)p - low) / (high - low);
  double maskv = 1.0 - fmin(fmax(ramp, 0.0), 1.0);
  float invf = (float)(interp * (1.0 - maskv) + extrap * maskv);

  float ang = (float)n * invf;     // fp32 multiply, matching reference rounding
  float s, c;
  sincosf(ang, &s, &c);
  const float conc = 1.3465735902799727f;  // 0.1*ln(32)+1
  c *= conc; s *= conc;

  float* base = qkv + (size_t)n * QKV_N + h * 64;
  float x1 = base[p], x2 = base[p + 32];
  base[p]      = x1 * c - x2 * s;
  base[p + 32] = x2 * c + x1 * s;
}

// ---------------- tf32 wmma GEMM: C[M,N] = A[M,K] @ B[K,N] (+ X residual) ----------------
template<int BM, int BN, int WM, int WN, bool RESID>
__global__ __launch_bounds__(256)
void gemm_tf32(const float* __restrict__ A, const float* __restrict__ B,
               const float* __restrict__ X, float* __restrict__ C,
               int M, int N, int K) {
  constexpr int BK = 32;
  constexpr int WARPS_M = BM / WM;
  constexpr int MF = WM / 16, NF = WN / 16;
  __shared__ float As[BM][BK + 4];
  __shared__ float Bs[BK][BN + 4];
  const int tid = threadIdx.x;
  const int wid = tid >> 5;
  const int wm = wid % WARPS_M;
  const int wn = wid / WARPS_M;
  const int bm = blockIdx.y * BM;
  const int bn = blockIdx.x * BN;

  wmma::fragment<wmma::accumulator, 16, 16, 8, float> cf[MF][NF];
  #pragma unroll
  for (int i = 0; i < MF; i++)
    #pragma unroll
    for (int j = 0; j < NF; j++) {
      if (RESID)
        wmma::load_matrix_sync(cf[i][j],
            X + (size_t)(bm + wm * WM + i * 16) * N + bn + wn * WN + j * 16,
            N, wmma::mem_row_major);
      else
        wmma::fill_fragment(cf[i][j], 0.0f);
    }

  const int arow = tid >> 3;
  const int acol = (tid & 7) << 2;
  constexpr int BTPR = BN / 4;
  const int brow = tid / BTPR;
  const int bcol = (tid % BTPR) << 2;
  constexpr int BRP = 256 / BTPR;

  for (int k0 = 0; k0 < K; k0 += BK) {
    #pragma unroll
    for (int p = 0; p < BM / 32; p++) {
      int r = arow + p * 32;
      *(float4*)&As[r][acol] = *(const float4*)(A + (size_t)(bm + r) * K + k0 + acol);
    }
    #pragma unroll
    for (int p = 0; p < BK / BRP; p++) {
      int r = brow + p * BRP;
      *(float4*)&Bs[r][bcol] = *(const float4*)(B + (size_t)(k0 + r) * N + bn + bcol);
    }
    __syncthreads();
    #pragma unroll
    for (int kk = 0; kk < BK / 8; kk++) {
      wmma::fragment<wmma::matrix_a, 16, 16, 8, wmma::precision::tf32, wmma::row_major> af[MF];
      wmma::fragment<wmma::matrix_b, 16, 16, 8, wmma::precision::tf32, wmma::row_major> bf[NF];
      #pragma unroll
      for (int i = 0; i < MF; i++) {
        wmma::load_matrix_sync(af[i], &As[wm * WM + i * 16][kk * 8], BK + 4);
        #pragma unroll
        for (int e = 0; e < af[i].num_elements; e++)
          af[i].x[e] = wmma::__float_to_tf32(af[i].x[e]);
      }
      #pragma unroll
      for (int j = 0; j < NF; j++) {
        wmma::load_matrix_sync(bf[j], &Bs[kk * 8][wn * WN + j * 16], BN + 4);
        #pragma unroll
        for (int e = 0; e < bf[j].num_elements; e++)
          bf[j].x[e] = wmma::__float_to_tf32(bf[j].x[e]);
      }
      #pragma unroll
      for (int i = 0; i < MF; i++)
        #pragma unroll
        for (int j = 0; j < NF; j++)
          wmma::mma_sync(cf[i][j], af[i], bf[j], cf[i][j]);
    }
    __syncthreads();
  }
  #pragma unroll
  for (int i = 0; i < MF; i++)
    #pragma unroll
    for (int j = 0; j < NF; j++)
      wmma::store_matrix_sync(C + (size_t)(bm + wm * WM + i * 16) * N + bn + wn * WN + j * 16,
                              cf[i][j], N, wmma::mem_row_major);
}

// ---------------- attention: sliding window 128 + sink, online softmax ----------------
// block: (qblock of 64, head). 256 threads. 3 key chunks of 64 covering [q0-128, q0+63].
#define ATTN_SMEM ((4096 + 64*65 + 4096 + 192) * 4)

__global__ __launch_bounds__(256) void attn_kernel(
    const float* __restrict__ qkv, const float* __restrict__ sinks, float* __restrict__ O) {
  extern __shared__ float sm[];
  float* Qs = sm;                  // [64][64]
  float* Ks = sm + 4096;           // [64][65] (reused for V)
  float* Ss = Ks + 64 * 65;        // [64][64] scores -> probabilities
  float* s_m   = Ss + 4096;        // [64]
  float* s_l   = s_m + 64;         // [64]
  float* s_fac = s_l + 64;         // [64]

  const int q0 = blockIdx.x * 64;
  const int head = blockIdx.y;
  const int kvh = head >> 3;
  const int tid = threadIdx.x;
  const int tq = tid >> 4;   // 0..15 (row group of 4)
  const int tk = tid & 15;   // 0..15 (col group of 4)

  // load Q tile (pre-scaled)
  for (int i = tid; i < 64 * 64; i += 256) {
    int r = i >> 6, d = i & 63;
    Qs[r * 64 + d] = qkv[(size_t)(q0 + r) * QKV_N + head * 64 + d] * SM_SCALE;
  }
  if (tid < 64) { s_m[tid] = -1e30f; s_l[tid] = 0.f; }

  float acc[4][4];
  #pragma unroll
  for (int i = 0; i < 4; i++)
    #pragma unroll
    for (int j = 0; j < 4; j++) acc[i][j] = 0.f;

  for (int cch = 0; cch < 3; cch++) {
    int k0 = q0 - 128 + cch * 64;
    if (k0 + 63 < 0) continue;     // entirely out of range (uniform per block)

    __syncthreads();               // prior PV done with Ks/Ss; Q/init visible
    // load K chunk
    for (int i = tid; i < 64 * 64; i += 256) {
      int r = i >> 6, d = i & 63;
      int j = k0 + r;
      Ks[r * 65 + d] = (j >= 0) ? qkv[(size_t)j * QKV_N + 4096 + kvh * 64 + d] : 0.f;
    }
    __syncthreads();

    // scores: 4x4 register tile per thread
    float s[4][4];
    #pragma unroll
    for (int i = 0; i < 4; i++)
      #pragma unroll
      for (int j = 0; j < 4; j++) s[i][j] = 0.f;
    #pragma unroll 8
    for (int d = 0; d < 64; d++) {
      float qv[4], kv[4];
      #pragma unroll
      for (int i = 0; i < 4; i++) qv[i] = Qs[(tq * 4 + i) * 64 + d];
      #pragma unroll
      for (int j = 0; j < 4; j++) kv[j] = Ks[(tk * 4 + j) * 65 + d];
      #pragma unroll
      for (int i = 0; i < 4; i++)
        #pragma unroll
        for (int j = 0; j < 4; j++) s[i][j] += qv[i] * kv[j];
    }
    #pragma unroll
    for (int i = 0; i < 4; i++) {
      int gi = q0 + tq * 4 + i;
      #pragma unroll
      for (int j = 0; j < 4; j++) {
        int gj = k0 + tk * 4 + j;
        bool ok = (gj >= 0) && (gj <= gi) && (gi - gj < 128);
        Ss[(tq * 4 + i) * 64 + tk * 4 + j] = ok ? s[i][j] : -1e30f;
      }
    }
    __syncthreads();

    // load V into Ks (K no longer needed)
    for (int i = tid; i < 64 * 64; i += 256) {
      int r = i >> 6, d = i & 63;
      int j = k0 + r;
      Ks[r * 65 + d] = (j >= 0) ? qkv[(size_t)j * QKV_N + 4608 + kvh * 64 + d] : 0.f;
    }

    // online-softmax row update: 4 threads per row
    {
      int r = tid >> 2, part = tid & 3;
      float cm = -1e30f;
      #pragma unroll
      for (int kk = 0; kk < 16; kk++) cm = fmaxf(cm, Ss[r * 64 + part * 16 + kk]);
      cm = fmaxf(cm, __shfl_xor_sync(0xffffffffu, cm, 1));
      cm = fmaxf(cm, __shfl_xor_sync(0xffffffffu, cm, 2));
      float mold = s_m[r];
      float mnew = fmaxf(mold, cm);
      float psum = 0.f;
      #pragma unroll
      for (int kk = 0; kk < 16; kk++) {
        float sv = Ss[r * 64 + part * 16 + kk];
        float p = (sv > -1e29f) ? __expf(sv - mnew) : 0.f;
        Ss[r * 64 + part * 16 + kk] = p;
        psum += p;
      }
      psum += __shfl_xor_sync(0xffffffffu, psum, 1);
      psum += __shfl_xor_sync(0xffffffffu, psum, 2);
      if (part == 0) {
        float fac = __expf(mold - mnew);
        s_fac[r] = fac;
        s_l[r] = s_l[r] * fac + psum;
        s_m[r] = mnew;
      }
    }
    __syncthreads();

    // PV: acc = acc*fac + P @ V  (4x4 register tile, same row ownership)
    float fr[4];
    #pragma unroll
    for (int i = 0; i < 4; i++) fr[i] = s_fac[tq * 4 + i];
    #pragma unroll
    for (int i = 0; i < 4; i++)
      #pragma unroll
      for (int j = 0; j < 4; j++) acc[i][j] *= fr[i];
    #pragma unroll 8
    for (int k = 0; k < 64; k++) {
      float pv[4], vv[4];
      #pragma unroll
      for (int i = 0; i < 4; i++) pv[i] = Ss[(tq * 4 + i) * 64 + k];
      #pragma unroll
      for (int j = 0; j < 4; j++) vv[j] = Ks[k * 65 + tk * 4 + j];
      #pragma unroll
      for (int i = 0; i < 4; i++)
        #pragma unroll
        for (int j = 0; j < 4; j++) acc[i][j] += pv[i] * vv[j];
    }
  }
  __syncthreads();

  // sink epilogue + write
  float S = sinks[head];
  #pragma unroll
  for (int i = 0; i < 4; i++) {
    int q = tq * 4 + i;
    int gi = q0 + q;
    float mold = s_m[q];
    float mf = fmaxf(mold, S);
    float fac = __expf(mold - mf);
    float f = fac / (s_l[q] * fac + __expf(S - mf));
    float4 o4 = make_float4(acc[i][0] * f, acc[i][1] * f, acc[i][2] * f, acc[i][3] * f);
    *(float4*)&O[(size_t)gi * ADIM + head * 64 + tk * 4] = o4;
  }
}

// ---------------- launch ----------------
extern "C" void kernel_launch(void* const* d_in, const int* in_sizes, int n_in,
                              void* d_out, int out_size) {
  const float* x      = (const float*)d_in[0];
  const float* norm_w = (const float*)d_in[1];
  const float* qkv_w  = (const float*)d_in[2];
  const float* out_w  = (const float*)d_in[3];
  const float* sinks  = (const float*)d_in[4];
  float* out = (float*)d_out;

  float *t, *qkv, *attn;
  cudaGetSymbolAddress((void**)&t, g_t);
  cudaGetSymbolAddress((void**)&qkv, g_qkv);
  cudaGetSymbolAddress((void**)&attn, g_attn);

  rmsnorm_kernel<<<N_TOK, 256>>>(x, norm_w, t);

  gemm_tf32<128, 128, 32, 64, false>
      <<<dim3(QKV_N / 128, N_TOK / 128), 256>>>(t, qkv_w, nullptr, qkv, N_TOK, QKV_N, HID);

  rope_kernel<<<(N_TOK * 72 * 32) / 256, 256>>>(qkv);

  cudaFuncSetAttribute(attn_kernel, cudaFuncAttributeMaxDynamicSharedMemorySize, ATTN_SMEM);
  attn_kernel<<<dim3(N_TOK / 64, 64), 256, ATTN_SMEM>>>(qkv, sinks, attn);

  gemm_tf32<128, 64, 32, 32, true>
      <<<dim3(HID / 64, N_TOK / 128), 256>>>(attn, out_w, x, out, N_TOK, HID, ADIM);
}

// round 4
// speedup vs baseline: 1.0923x; 1.0923x over previous
#include <cuda_runtime.h>
#include <cstdint>
#include <mma.h>
#include <math.h>

using namespace nvcuda;

#define N_TOK 2048
#define HID   2880
#define QKV_N 5120   // 64*64 q + 8*64 k + 8*64 v
#define ADIM  4096   // 64 heads * 64 dim
#define SM_SCALE 0.125f

// ---------------- scratch (no allocs allowed) ----------------
__device__ float g_t[N_TOK * HID];      // rmsnorm output
__device__ float g_qkv[N_TOK * QKV_N];  // qkv projection (rope applied in place)
__device__ float g_attn[N_TOK * ADIM];  // attention output

// ---------------- cp.async helpers ----------------
__device__ __forceinline__ void cp_async16(void* smem, const void* gmem) {
  unsigned int s = (unsigned int)__cvta_generic_to_shared(smem);
  asm volatile("cp.async.cg.shared.global [%0], [%1], 16;\n" :: "r"(s), "l"(gmem));
}
__device__ __forceinline__ void cp_commit() {
  asm volatile("cp.async.commit_group;\n");
}
__device__ __forceinline__ void cp_wait0() {
  asm volatile("cp.async.wait_group 0;\n");
}

// ---------------- RMSNorm ----------------
__global__ __launch_bounds__(256) void rmsnorm_kernel(
    const float* __restrict__ x, const float* __restrict__ w, float* __restrict__ t) {
  int row = blockIdx.x;
  const float* xr = x + (size_t)row * HID;
  float* tr = t + (size_t)row * HID;
  float ss = 0.f;
  for (int i = threadIdx.x; i < HID; i += 256) { float v = xr[i]; ss += v * v; }
  #pragma unroll
  for (int o = 16; o; o >>= 1) ss += __shfl_xor_sync(0xffffffffu, ss, o);
  __shared__ float red[8];
  __shared__ float s_inv;
  if ((threadIdx.x & 31) == 0) red[threadIdx.x >> 5] = ss;
  __syncthreads();
  if (threadIdx.x == 0) {
    float tot = 0.f;
    #pragma unroll
    for (int i = 0; i < 8; i++) tot += red[i];
    s_inv = rsqrtf(tot / (float)HID + 1e-5f);
  }
  __syncthreads();
  float inv = s_inv;
  for (int i = threadIdx.x; i < HID; i += 256) tr[i] = xr[i] * inv * w[i];
}

// ---------------- RoPE (YaRN/NTK), in place on q (heads 0..63) and k (heads 64..71) ----------------
__global__ void rope_kernel(float* __restrict__ qkv) {
  int idx = blockIdx.x * blockDim.x + threadIdx.x;
  if (idx >= N_TOK * 72 * 32) return;
  int p = idx & 31;                // dim pair 0..31
  int h = (idx >> 5) % 72;         // head slot (q:0..63, k:64..71; both at offset h*64)
  int n = idx / (32 * 72);         // token

  const double LOGB = 11.918390573078392;  // ln(150000)
  double freq = exp((double)p * (LOGB / 32.0));
  double interp = 1.0 / (32.0 * freq);
  double extrap = 1.0 / freq;
  double low  = 32.0 * log(4096.0 / (32.0 * 2.0 * M_PI)) / LOGB;
  double high = 32.0 * log(4096.0 / (2.0 * M_PI)) / LOGB;
  double ramp = ((double)p - low) / (high - low);
  double maskv = 1.0 - fmin(fmax(ramp, 0.0), 1.0);
  float invf = (float)(interp * (1.0 - maskv) + extrap * maskv);

  float ang = (float)n * invf;     // fp32 multiply, matching reference rounding
  float s, c;
  sincosf(ang, &s, &c);
  const float conc = 1.3465735902799727f;  // 0.1*ln(32)+1
  c *= conc; s *= conc;

  float* base = qkv + (size_t)n * QKV_N + h * 64;
  float x1 = base[p], x2 = base[p + 32];
  base[p]      = x1 * c - x2 * s;
  base[p + 32] = x2 * c + x1 * s;
}

// ---------------- tf32 wmma GEMM, cp.async 2-stage pipeline ----------------
// C[M,N] = A[M,K] @ B[K,N] (+ X residual)
template<int BM, int BN, int WM, int WN, bool RESID>
__global__ __launch_bounds__(256)
void gemm_tf32(const float* __restrict__ A, const float* __restrict__ B,
               const float* __restrict__ X, float* __restrict__ C,
               int M, int N, int K) {
  constexpr int BK = 32;
  constexpr int WARPS_M = BM / WM;
  constexpr int MF = WM / 16, NF = WN / 16;
  constexpr int ASTRIDE = BK + 4;   // floats; row pitch 144B (16B-aligned)
  constexpr int BSTRIDE = BN + 4;   // floats; 16B-aligned pitch
  extern __shared__ float sh[];
  float* As = sh;                          // [2][BM][ASTRIDE]
  float* Bs = sh + 2 * BM * ASTRIDE;       // [2][BK][BSTRIDE]

  const int tid = threadIdx.x;
  const int wid = tid >> 5;
  const int wm = wid % WARPS_M;
  const int wn = wid / WARPS_M;
  const int bm = blockIdx.y * BM;
  const int bn = blockIdx.x * BN;

  // global->shared thread mapping (16B per cp.async)
  const int arow = tid >> 3;              // 0..31
  const int acol = (tid & 7) << 2;        // 0,4,..,28
  constexpr int BTPR = BN / 4;            // threads per B row
  const int brow = tid / BTPR;
  const int bcol = (tid % BTPR) << 2;
  constexpr int BRP = 256 / BTPR;         // B rows per pass

  wmma::fragment<wmma::accumulator, 16, 16, 8, float> cf[MF][NF];
  #pragma unroll
  for (int i = 0; i < MF; i++)
    #pragma unroll
    for (int j = 0; j < NF; j++) {
      if (RESID)
        wmma::load_matrix_sync(cf[i][j],
            X + (size_t)(bm + wm * WM + i * 16) * N + bn + wn * WN + j * 16,
            N, wmma::mem_row_major);
      else
        wmma::fill_fragment(cf[i][j], 0.0f);
    }

  auto issue = [&](int stage, int k0) {
    float* as = As + stage * BM * ASTRIDE;
    #pragma unroll
    for (int p = 0; p < BM / 32; p++) {
      int r = arow + p * 32;
      cp_async16(&as[r * ASTRIDE + acol], A + (size_t)(bm + r) * K + k0 + acol);
    }
    float* bs = Bs + stage * BK * BSTRIDE;
    #pragma unroll
    for (int p = 0; p < BK / BRP; p++) {
      int r = brow + p * BRP;
      cp_async16(&bs[r * BSTRIDE + bcol], B + (size_t)(k0 + r) * N + bn + bcol);
    }
    cp_commit();
  };

  const int nk = K / BK;
  issue(0, 0);
  int s = 0;
  for (int kt = 0; kt < nk; kt++) {
    cp_wait0();
    __syncthreads();
    if (kt + 1 < nk) issue(s ^ 1, (kt + 1) * BK);

    float* as = As + s * BM * ASTRIDE;
    float* bs = Bs + s * BK * BSTRIDE;
    #pragma unroll
    for (int kk = 0; kk < BK / 8; kk++) {
      wmma::fragment<wmma::matrix_a, 16, 16, 8, wmma::precision::tf32, wmma::row_major> af[MF];
      wmma::fragment<wmma::matrix_b, 16, 16, 8, wmma::precision::tf32, wmma::row_major> bf[NF];
      #pragma unroll
      for (int i = 0; i < MF; i++) {
        wmma::load_matrix_sync(af[i], &as[(wm * WM + i * 16) * ASTRIDE + kk * 8], ASTRIDE);
        #pragma unroll
        for (int e = 0; e < af[i].num_elements; e++)
          af[i].x[e] = wmma::__float_to_tf32(af[i].x[e]);
      }
      #pragma unroll
      for (int j = 0; j < NF; j++) {
        wmma::load_matrix_sync(bf[j], &bs[(kk * 8) * BSTRIDE + wn * WN + j * 16], BSTRIDE);
        #pragma unroll
        for (int e = 0; e < bf[j].num_elements; e++)
          bf[j].x[e] = wmma::__float_to_tf32(bf[j].x[e]);
      }
      #pragma unroll
      for (int i = 0; i < MF; i++)
        #pragma unroll
        for (int j = 0; j < NF; j++)
          wmma::mma_sync(cf[i][j], af[i], bf[j], cf[i][j]);
    }
    __syncthreads();
    s ^= 1;
  }
  #pragma unroll
  for (int i = 0; i < MF; i++)
    #pragma unroll
    for (int j = 0; j < NF; j++)
      wmma::store_matrix_sync(C + (size_t)(bm + wm * WM + i * 16) * N + bn + wn * WN + j * 16,
                              cf[i][j], N, wmma::mem_row_major);
}

// ---------------- attention: sliding window 128 + sink, online softmax ----------------
#define ATTN_SMEM ((4096 + 64*65 + 4096 + 192) * 4)

__global__ __launch_bounds__(256) void attn_kernel(
    const float* __restrict__ qkv, const float* __restrict__ sinks, float* __restrict__ O) {
  extern __shared__ float sm[];
  float* Qs = sm;                  // [64][64]
  float* Ks = sm + 4096;           // [64][65] (reused for V)
  float* Ss = Ks + 64 * 65;        // [64][64] scores -> probabilities
  float* s_m   = Ss + 4096;        // [64]
  float* s_l   = s_m + 64;         // [64]
  float* s_fac = s_l + 64;         // [64]

  const int q0 = blockIdx.x * 64;
  const int head = blockIdx.y;
  const int kvh = head >> 3;
  const int tid = threadIdx.x;
  const int tq = tid >> 4;   // 0..15
  const int tk = tid & 15;   // 0..15

  for (int i = tid; i < 64 * 64; i += 256) {
    int r = i >> 6, d = i & 63;
    Qs[r * 64 + d] = qkv[(size_t)(q0 + r) * QKV_N + head * 64 + d] * SM_SCALE;
  }
  if (tid < 64) { s_m[tid] = -1e30f; s_l[tid] = 0.f; }

  float acc[4][4];
  #pragma unroll
  for (int i = 0; i < 4; i++)
    #pragma unroll
    for (int j = 0; j < 4; j++) acc[i][j] = 0.f;

  for (int cch = 0; cch < 3; cch++) {
    int k0 = q0 - 128 + cch * 64;
    if (k0 + 63 < 0) continue;

    __syncthreads();
    for (int i = tid; i < 64 * 64; i += 256) {
      int r = i >> 6, d = i & 63;
      int j = k0 + r;
      Ks[r * 65 + d] = (j >= 0) ? qkv[(size_t)j * QKV_N + 4096 + kvh * 64 + d] : 0.f;
    }
    __syncthreads();

    float s[4][4];
    #pragma unroll
    for (int i = 0; i < 4; i++)
      #pragma unroll
      for (int j = 0; j < 4; j++) s[i][j] = 0.f;
    #pragma unroll 8
    for (int d = 0; d < 64; d++) {
      float qv[4], kv[4];
      #pragma unroll
      for (int i = 0; i < 4; i++) qv[i] = Qs[(tq * 4 + i) * 64 + d];
      #pragma unroll
      for (int j = 0; j < 4; j++) kv[j] = Ks[(tk * 4 + j) * 65 + d];
      #pragma unroll
      for (int i = 0; i < 4; i++)
        #pragma unroll
        for (int j = 0; j < 4; j++) s[i][j] += qv[i] * kv[j];
    }
    #pragma unroll
    for (int i = 0; i < 4; i++) {
      int gi = q0 + tq * 4 + i;
      #pragma unroll
      for (int j = 0; j < 4; j++) {
        int gj = k0 + tk * 4 + j;
        bool ok = (gj >= 0) && (gj <= gi) && (gi - gj < 128);
        Ss[(tq * 4 + i) * 64 + tk * 4 + j] = ok ? s[i][j] : -1e30f;
      }
    }
    __syncthreads();

    for (int i = tid; i < 64 * 64; i += 256) {
      int r = i >> 6, d = i & 63;
      int j = k0 + r;
      Ks[r * 65 + d] = (j >= 0) ? qkv[(size_t)j * QKV_N + 4608 + kvh * 64 + d] : 0.f;
    }

    {
      int r = tid >> 2, part = tid & 3;
      float cm = -1e30f;
      #pragma unroll
      for (int kk = 0; kk < 16; kk++) cm = fmaxf(cm, Ss[r * 64 + part * 16 + kk]);
      cm = fmaxf(cm, __shfl_xor_sync(0xffffffffu, cm, 1));
      cm = fmaxf(cm, __shfl_xor_sync(0xffffffffu, cm, 2));
      float mold = s_m[r];
      float mnew = fmaxf(mold, cm);
      float psum = 0.f;
      #pragma unroll
      for (int kk = 0; kk < 16; kk++) {
        float sv = Ss[r * 64 + part * 16 + kk];
        float p = (sv > -1e29f) ? __expf(sv - mnew) : 0.f;
        Ss[r * 64 + part * 16 + kk] = p;
        psum += p;
      }
      psum += __shfl_xor_sync(0xffffffffu, psum, 1);
      psum += __shfl_xor_sync(0xffffffffu, psum, 2);
      if (part == 0) {
        float fac = __expf(mold - mnew);
        s_fac[r] = fac;
        s_l[r] = s_l[r] * fac + psum;
        s_m[r] = mnew;
      }
    }
    __syncthreads();

    float fr[4];
    #pragma unroll
    for (int i = 0; i < 4; i++) fr[i] = s_fac[tq * 4 + i];
    #pragma unroll
    for (int i = 0; i < 4; i++)
      #pragma unroll
      for (int j = 0; j < 4; j++) acc[i][j] *= fr[i];
    #pragma unroll 8
    for (int k = 0; k < 64; k++) {
      float pv[4], vv[4];
      #pragma unroll
      for (int i = 0; i < 4; i++) pv[i] = Ss[(tq * 4 + i) * 64 + k];
      #pragma unroll
      for (int j = 0; j < 4; j++) vv[j] = Ks[k * 65 + tk * 4 + j];
      #pragma unroll
      for (int i = 0; i < 4; i++)
        #pragma unroll
        for (int j = 0; j < 4; j++) acc[i][j] += pv[i] * vv[j];
    }
  }
  __syncthreads();

  float S = sinks[head];
  #pragma unroll
  for (int i = 0; i < 4; i++) {
    int q = tq * 4 + i;
    int gi = q0 + q;
    float mold = s_m[q];
    float mf = fmaxf(mold, S);
    float fac = __expf(mold - mf);
    float f = fac / (s_l[q] * fac + __expf(S - mf));
    float4 o4 = make_float4(acc[i][0] * f, acc[i][1] * f, acc[i][2] * f, acc[i][3] * f);
    *(float4*)&O[(size_t)gi * ADIM + head * 64 + tk * 4] = o4;
  }
}

// ---------------- launch ----------------
extern "C" void kernel_launch(void* const* d_in, const int* in_sizes, int n_in,
                              void* d_out, int out_size) {
  const float* x      = (const float*)d_in[0];
  const float* norm_w = (const float*)d_in[1];
  const float* qkv_w  = (const float*)d_in[2];
  const float* out_w  = (const float*)d_in[3];
  const float* sinks  = (const float*)d_in[4];
  float* out = (float*)d_out;

  float *t, *qkv, *attn;
  cudaGetSymbolAddress((void**)&t, g_t);
  cudaGetSymbolAddress((void**)&qkv, g_qkv);
  cudaGetSymbolAddress((void**)&attn, g_attn);

  rmsnorm_kernel<<<N_TOK, 256>>>(x, norm_w, t);

  // qkv GEMM: M=2048, N=5120, K=2880
  {
    constexpr int SMEM = (2 * 128 * 36 + 2 * 32 * 132) * 4;  // 70656 B
    cudaFuncSetAttribute((const void*)gemm_tf32<128, 128, 64, 32, false>,
                         cudaFuncAttributeMaxDynamicSharedMemorySize, SMEM);
    gemm_tf32<128, 128, 64, 32, false>
        <<<dim3(QKV_N / 128, N_TOK / 128), 256, SMEM>>>(t, qkv_w, nullptr, qkv,
                                                        N_TOK, QKV_N, HID);
  }

  rope_kernel<<<(N_TOK * 72 * 32) / 256, 256>>>(qkv);

  cudaFuncSetAttribute(attn_kernel, cudaFuncAttributeMaxDynamicSharedMemorySize, ATTN_SMEM);
  attn_kernel<<<dim3(N_TOK / 64, 64), 256, ATTN_SMEM>>>(qkv, sinks, attn);

  // out GEMM: M=2048, N=2880, K=4096 (+ residual)
  {
    constexpr int SMEM = (2 * 128 * 36 + 2 * 32 * 68) * 4;  // 54272 B
    cudaFuncSetAttribute((const void*)gemm_tf32<128, 64, 32, 32, true>,
                         cudaFuncAttributeMaxDynamicSharedMemorySize, SMEM);
    gemm_tf32<128, 64, 32, 32, true>
        <<<dim3(HID / 64, N_TOK / 128), 256, SMEM>>>(attn, out_w, x, out,
                                                     N_TOK, HID, ADIM);
  }
}